// round 15
// baseline (speedup 1.0000x reference)
#include <cuda_runtime.h>
#include <math.h>
#include <stdint.h>

// IterNormRotation: X (32,512,56,56) fp32, rot (1,512,512) fp32, T=10.
//   S = X Xᵀ (Gram over m=B*H*W) via tf32 MMA (+ fused channel sums)
//   Sigma = eps I + S/m - mu muᵀ ; rTr = 1/tr ; SN = Sigma*rTr ; P = I
//   10x NS: P = 1.5P - 0.5 (P@P)@(P@SN)   — persistent kernel, compensated tf32
//   M = sqrt(rTr) * rot @ P ; bias = M@mu  (inside the persistent kernel)
//   out = M @ X - bias  via tf32 MMA

#define Cc   512
#define Bb   32
#define HWs  3136
#define MTOTf 100352.0f
#define EPSf 1e-5f
#define NS_ITERS 10

#define GP 36     // pitch for [row][k] tiles (k=32) -> frag bank 4g+tig (CF)
#define BP 136    // pitch for [k][n] tiles (n=128)  -> frag bank 8tig+g (CF)
#define NBP 40    // pitch for [k][n] tiles (n=32)   -> frag bank 8tig+g (CF)

#define NS_NB 256u   // persistent grid size

__device__ float g_S [Cc*Cc];
__device__ float g_SN[Cc*Cc];
__device__ float g_P [Cc*Cc];
__device__ float g_T1[Cc*Cc];
__device__ float g_T2[Cc*Cc];
__device__ float g_M [Cc*Cc];
__device__ float g_sum [Cc];
__device__ float g_mean[Cc];
__device__ float g_bias[Cc];
__device__ float g_scal[2];        // [0]=rTr, [1]=sqrt(rTr)
__device__ unsigned g_bar_cnt;
__device__ unsigned g_bar_rel;

// ---------------------------------------------------------------- helpers
__device__ __forceinline__ uint32_t f2tf(float f) {
    uint32_t u; asm("cvt.rna.tf32.f32 %0, %1;" : "=r"(u) : "f"(f)); return u;
}

__device__ __forceinline__ void mma8(float* d, const uint32_t* a, const uint32_t* b) {
    asm volatile(
        "mma.sync.aligned.m16n8k8.row.col.f32.tf32.tf32.f32 "
        "{%0,%1,%2,%3}, {%4,%5,%6,%7}, {%8,%9}, {%0,%1,%2,%3};\n"
        : "+f"(d[0]), "+f"(d[1]), "+f"(d[2]), "+f"(d[3])
        : "r"(a[0]), "r"(a[1]), "r"(a[2]), "r"(a[3]), "r"(b[0]), "r"(b[1]));
}

// grid-wide barrier (all NS_NB blocks co-resident; gen = 1,2,3,...)
__device__ __forceinline__ void gsync(unsigned gen) {
    __syncthreads();
    if (threadIdx.x == 0) {
        __threadfence();
        unsigned arrived = atomicAdd(&g_bar_cnt, 1u) + 1u;
        if (arrived == gen * NS_NB) {
            asm volatile("st.release.gpu.global.u32 [%0], %1;"
                         :: "l"(&g_bar_rel), "r"(gen) : "memory");
        } else {
            unsigned r;
            do {
                asm volatile("ld.acquire.gpu.global.u32 %0, [%1];"
                             : "=r"(r) : "l"(&g_bar_rel) : "memory");
            } while (r < gen);
        }
    }
    __syncthreads();
}

// ---------------------------------------------------------------- zero
__global__ void k_zero() {
    int idx = blockIdx.x * blockDim.x + threadIdx.x;
    if (idx < Cc*Cc) g_S[idx] = 0.f;
    if (idx < Cc)    g_sum[idx] = 0.f;
    if (idx == 0) { g_bar_cnt = 0u; g_bar_rel = 0u; }
}

// ---------------------------------------------------------------- Gram (tf32 MMA)
// 128x128 tile per (pair, batch), BK=32, 8 warps of 64x32 warp-tiles.
// Diagonal-pair blocks skip the B-panel load (A==B) and also accumulate
// per-channel sums.
__global__ void __launch_bounds__(256, 2) k_gram(const float* __restrict__ X) {
    int p = blockIdx.x;
    int it = 0, rem = p;
    while (rem >= 4 - it) { rem -= 4 - it; it++; }
    int jt = it + rem;
    int b  = blockIdx.y;
    bool diag = (it == jt);

    int i0 = it * 128, j0 = jt * 128;
    const float* Xb = X + (size_t)b * Cc * HWs;

    __shared__ uint32_t As[128 * GP];   // [row 0..127][k 0..31]
    __shared__ uint32_t Bs[128 * GP];

    int tid  = threadIdx.x;
    int lane = tid & 31, warp = tid >> 5;
    int g = lane >> 2, tig = lane & 3;
    int wm = (warp >> 2) * 64;
    int wn = (warp & 3) * 32;

    float acc[4][4][4];
    #pragma unroll
    for (int mt = 0; mt < 4; mt++)
        #pragma unroll
        for (int nt = 0; nt < 4; nt++)
            #pragma unroll
            for (int i = 0; i < 4; i++) acc[mt][nt][i] = 0.f;

    float rsum[4] = {0.f, 0.f, 0.f, 0.f};

    const uint32_t* Bsel = diag ? As : Bs;

    for (int k0 = 0; k0 < HWs; k0 += 32) {
        #pragma unroll
        for (int l = 0; l < 4; l++) {
            int e   = tid + l * 256;
            int row = e >> 3;
            int kq  = (e & 7) * 4;
            float4 va = *(const float4*)(Xb + (size_t)(i0 + row) * HWs + k0 + kq);
            *(uint4*)&As[row * GP + kq] =
                make_uint4(f2tf(va.x), f2tf(va.y), f2tf(va.z), f2tf(va.w));
            if (diag) {
                rsum[l] += (va.x + va.y) + (va.z + va.w);
            } else {
                float4 vb = *(const float4*)(Xb + (size_t)(j0 + row) * HWs + k0 + kq);
                *(uint4*)&Bs[row * GP + kq] =
                    make_uint4(f2tf(vb.x), f2tf(vb.y), f2tf(vb.z), f2tf(vb.w));
            }
        }
        __syncthreads();

        #pragma unroll
        for (int ks = 0; ks < 32; ks += 8) {
            uint32_t af[4][4], bf[4][2];
            #pragma unroll
            for (int mt = 0; mt < 4; mt++) {
                int r = wm + mt * 16 + g;
                af[mt][0] = As[r       * GP + ks + tig];
                af[mt][1] = As[(r + 8) * GP + ks + tig];
                af[mt][2] = As[r       * GP + ks + tig + 4];
                af[mt][3] = As[(r + 8) * GP + ks + tig + 4];
            }
            #pragma unroll
            for (int nt = 0; nt < 4; nt++) {
                int c = wn + nt * 8 + g;
                bf[nt][0] = Bsel[c * GP + ks + tig];
                bf[nt][1] = Bsel[c * GP + ks + tig + 4];
            }
            #pragma unroll
            for (int mt = 0; mt < 4; mt++)
                #pragma unroll
                for (int nt = 0; nt < 4; nt++)
                    mma8(acc[mt][nt], af[mt], bf[nt]);
        }
        __syncthreads();
    }

    if (diag) {
        #pragma unroll
        for (int l = 0; l < 4; l++) {
            int row = (tid + l * 256) >> 3;
            atomicAdd(&g_sum[i0 + row], rsum[l]);
        }
    }

    bool mirror = !diag;
    #pragma unroll
    for (int mt = 0; mt < 4; mt++) {
        int m_ = wm + mt * 16 + g;
        #pragma unroll
        for (int nt = 0; nt < 4; nt++) {
            int n_ = wn + nt * 8 + 2 * tig;
            int gi0 = i0 + m_, gi1 = gi0 + 8;
            int gj0 = j0 + n_, gj1 = gj0 + 1;
            atomicAdd(&g_S[gi0 * Cc + gj0], acc[mt][nt][0]);
            atomicAdd(&g_S[gi0 * Cc + gj1], acc[mt][nt][1]);
            atomicAdd(&g_S[gi1 * Cc + gj0], acc[mt][nt][2]);
            atomicAdd(&g_S[gi1 * Cc + gj1], acc[mt][nt][3]);
            if (mirror) {
                atomicAdd(&g_S[gj0 * Cc + gi0], acc[mt][nt][0]);
                atomicAdd(&g_S[gj1 * Cc + gi0], acc[mt][nt][1]);
                atomicAdd(&g_S[gj0 * Cc + gi1], acc[mt][nt][2]);
                atomicAdd(&g_S[gj1 * Cc + gi1], acc[mt][nt][3]);
            }
        }
    }
}

// ---------------------------------------------------------------- persistent NS
// 64x32 compensated-tf32 tile: D = alpha*(A@B) + beta*Cin.
// 256 threads: 8 warps, each 32m x 8n (mt=2). Software-pipelined loads.
struct NsSmem {
    uint32_t Ah[64 * GP];
    uint32_t Al[64 * GP];
    uint32_t Bh[32 * NBP];
    uint32_t Bl[32 * NBP];
    float red[8];
};

__device__ __forceinline__ void ns_tile(
    NsSmem* sm,
    const float* __restrict__ A, const float* __restrict__ Bm,
    const float* __restrict__ Cin, float* __restrict__ D,
    float alpha, float beta, int i0, int j0)
{
    int tid  = threadIdx.x;
    int lane = tid & 31, warp = tid >> 5;
    int g = lane >> 2, tig = lane & 3;
    int wm = (warp >> 2) * 32;
    int wn = (warp & 3) * 8;

    // per-thread load slots
    int rowA0 = tid >> 3,            kqA = (tid & 7) * 4;
    int rowA1 = (tid + 256) >> 3;
    int krB   = tid >> 3,            nqB = (tid & 7) * 4;

    float acc[2][4];
    #pragma unroll
    for (int mt = 0; mt < 2; mt++)
        #pragma unroll
        for (int i = 0; i < 4; i++) acc[mt][i] = 0.f;

    float4 ra0, ra1, rb;
    ra0 = *(const float4*)(A + (size_t)(i0 + rowA0) * Cc + kqA);
    ra1 = *(const float4*)(A + (size_t)(i0 + rowA1) * Cc + kqA);
    rb  = *(const float4*)(Bm + (size_t)krB * Cc + j0 + nqB);

    for (int k0 = 0; k0 < Cc; k0 += 32) {
        // split & store current slab
        {
            uint4 h, lo;
            h.x = f2tf(ra0.x); lo.x = f2tf(ra0.x - __uint_as_float(h.x));
            h.y = f2tf(ra0.y); lo.y = f2tf(ra0.y - __uint_as_float(h.y));
            h.z = f2tf(ra0.z); lo.z = f2tf(ra0.z - __uint_as_float(h.z));
            h.w = f2tf(ra0.w); lo.w = f2tf(ra0.w - __uint_as_float(h.w));
            *(uint4*)&sm->Ah[rowA0 * GP + kqA] = h;
            *(uint4*)&sm->Al[rowA0 * GP + kqA] = lo;
            h.x = f2tf(ra1.x); lo.x = f2tf(ra1.x - __uint_as_float(h.x));
            h.y = f2tf(ra1.y); lo.y = f2tf(ra1.y - __uint_as_float(h.y));
            h.z = f2tf(ra1.z); lo.z = f2tf(ra1.z - __uint_as_float(h.z));
            h.w = f2tf(ra1.w); lo.w = f2tf(ra1.w - __uint_as_float(h.w));
            *(uint4*)&sm->Ah[rowA1 * GP + kqA] = h;
            *(uint4*)&sm->Al[rowA1 * GP + kqA] = lo;
            h.x = f2tf(rb.x); lo.x = f2tf(rb.x - __uint_as_float(h.x));
            h.y = f2tf(rb.y); lo.y = f2tf(rb.y - __uint_as_float(h.y));
            h.z = f2tf(rb.z); lo.z = f2tf(rb.z - __uint_as_float(h.z));
            h.w = f2tf(rb.w); lo.w = f2tf(rb.w - __uint_as_float(h.w));
            *(uint4*)&sm->Bh[krB * NBP + nqB] = h;
            *(uint4*)&sm->Bl[krB * NBP + nqB] = lo;
        }
        __syncthreads();

        // prefetch next slab (overlaps MMA work below)
        if (k0 + 32 < Cc) {
            int kn = k0 + 32;
            ra0 = *(const float4*)(A + (size_t)(i0 + rowA0) * Cc + kn + kqA);
            ra1 = *(const float4*)(A + (size_t)(i0 + rowA1) * Cc + kn + kqA);
            rb  = *(const float4*)(Bm + (size_t)(kn + krB) * Cc + j0 + nqB);
        }

        #pragma unroll
        for (int ks = 0; ks < 32; ks += 8) {
            uint32_t ah[2][4], al2[2][4], bh2[2], bl2[2];
            #pragma unroll
            for (int mt = 0; mt < 2; mt++) {
                int r = wm + mt * 16 + g;
                ah[mt][0]  = sm->Ah[r       * GP + ks + tig];
                ah[mt][1]  = sm->Ah[(r + 8) * GP + ks + tig];
                ah[mt][2]  = sm->Ah[r       * GP + ks + tig + 4];
                ah[mt][3]  = sm->Ah[(r + 8) * GP + ks + tig + 4];
                al2[mt][0] = sm->Al[r       * GP + ks + tig];
                al2[mt][1] = sm->Al[(r + 8) * GP + ks + tig];
                al2[mt][2] = sm->Al[r       * GP + ks + tig + 4];
                al2[mt][3] = sm->Al[(r + 8) * GP + ks + tig + 4];
            }
            int c = wn + g;
            bh2[0] = sm->Bh[(ks + tig)     * NBP + c];
            bh2[1] = sm->Bh[(ks + tig + 4) * NBP + c];
            bl2[0] = sm->Bl[(ks + tig)     * NBP + c];
            bl2[1] = sm->Bl[(ks + tig + 4) * NBP + c];
            #pragma unroll
            for (int mt = 0; mt < 2; mt++) {
                mma8(acc[mt], ah[mt],  bh2);
                mma8(acc[mt], ah[mt],  bl2);
                mma8(acc[mt], al2[mt], bh2);
            }
        }
        __syncthreads();
    }

    #pragma unroll
    for (int mt = 0; mt < 2; mt++) {
        int gi0 = i0 + wm + mt * 16 + g;
        int gi1 = gi0 + 8;
        int col = j0 + wn + 2 * tig;
        float2 v0 = make_float2(alpha * acc[mt][0], alpha * acc[mt][1]);
        float2 v1 = make_float2(alpha * acc[mt][2], alpha * acc[mt][3]);
        if (Cin) {
            float2 c0 = *(const float2*)(Cin + (size_t)gi0 * Cc + col);
            float2 c1 = *(const float2*)(Cin + (size_t)gi1 * Cc + col);
            v0.x += beta * c0.x; v0.y += beta * c0.y;
            v1.x += beta * c1.x; v1.y += beta * c1.y;
        }
        *(float2*)(D + (size_t)gi0 * Cc + col) = v0;
        *(float2*)(D + (size_t)gi1 * Cc + col) = v1;
    }
}

__global__ void __launch_bounds__(256, 2) k_ns(const float* __restrict__ rot) {
    __shared__ NsSmem sm;
    int tid = threadIdx.x;
    int bid = blockIdx.x;
    unsigned gen = 0;

    // ---- prep1 (block 0): means, trace, scales
    if (bid == 0) {
        float t = 0.f;
        #pragma unroll
        for (int r = 0; r < 2; r++) {
            int c = tid + r * 256;
            float mean = g_sum[c] * (1.0f / MTOTf);
            g_mean[c] = mean;
            t += EPSf + g_S[c * Cc + c] * (1.0f / MTOTf) - mean * mean;
        }
        #pragma unroll
        for (int o = 16; o > 0; o >>= 1) t += __shfl_down_sync(0xffffffffu, t, o);
        if ((tid & 31) == 0) sm.red[tid >> 5] = t;
        __syncthreads();
        if (tid < 8) {
            float v = sm.red[tid];
            #pragma unroll
            for (int o = 4; o > 0; o >>= 1) v += __shfl_down_sync(0x000000ffu, v, o);
            if (tid == 0) {
                float rtr = 1.0f / v;
                g_scal[0] = rtr;
                g_scal[1] = sqrtf(rtr);
            }
        }
    }
    gsync(++gen);

    // ---- prep2 (all blocks): SN, P=I   (4 elems/thread)
    {
        float rtr = g_scal[0];
        int base = bid * 256 + tid;
        #pragma unroll
        for (int r = 0; r < 4; r++) {
            int idx = base + r * 65536;
            int i = idx >> 9, j = idx & 511;
            float v = g_S[idx] * (1.0f / MTOTf) - g_mean[i] * g_mean[j];
            if (i == j) v += EPSf;
            g_SN[idx] = v * rtr;
            g_P[idx]  = (i == j) ? 1.0f : 0.0f;
        }
    }
    gsync(++gen);

    // ---- Newton-Schulz
    for (int t = 0; t < NS_ITERS; t++) {
        // phase A: T1 = P@P (blocks 0..127), T2 = P@SN (blocks 128..255)
        {
            int tile = bid & 127;
            int i0 = (tile >> 4) * 64;
            int j0 = (tile & 15) * 32;
            ns_tile(&sm, g_P, (bid < 128) ? g_P : g_SN, nullptr,
                    (bid < 128) ? g_T1 : g_T2, 1.0f, 0.0f, i0, j0);
        }
        gsync(++gen);
        // phase B: P = 1.5P - 0.5 T1@T2 (blocks 0..127)
        if (bid < 128) {
            int i0 = (bid >> 4) * 64;
            int j0 = (bid & 15) * 32;
            ns_tile(&sm, g_T1, g_T2, g_P, g_P, -0.5f, 1.5f, i0, j0);
        }
        gsync(++gen);
    }

    // ---- M = sqrt(rTr) * rot @ P  (blocks 0..127)
    if (bid < 128) {
        int i0 = (bid >> 4) * 64;
        int j0 = (bid & 15) * 32;
        ns_tile(&sm, rot, g_P, nullptr, g_M, g_scal[1], 0.0f, i0, j0);
    }
    gsync(++gen);

    // ---- bias = M @ mean  (blocks 0..63, 8 warps x 1 row)
    if (bid < 64) {
        int warp = tid >> 5, lane = tid & 31;
        int d = bid * 8 + warp;
        float s = 0.f;
        for (int c = lane; c < Cc; c += 32) s += g_M[d * Cc + c] * g_mean[c];
        #pragma unroll
        for (int o = 16; o > 0; o >>= 1) s += __shfl_down_sync(0xffffffffu, s, o);
        if (lane == 0) g_bias[d] = s;
    }
}

// ---------------------------------------------------------------- out = M @ X - bias (tf32 MMA)
// per-batch 512x3136: 128x128 tiles, BK=32, 8 warps of 64x32.
__global__ void __launch_bounds__(256, 2) k_out(const float* __restrict__ X,
                                                float* __restrict__ Out)
{
    int j0 = blockIdx.x * 128;
    int i0 = blockIdx.y * 128;
    int b  = blockIdx.z;

    const float* Xb = X + (size_t)b * Cc * HWs;

    __shared__ uint32_t As[128 * GP];   // M tile  [m][k]
    __shared__ uint32_t Bs[32 * BP];    // X tile  [k][n]

    int tid  = threadIdx.x;
    int lane = tid & 31, warp = tid >> 5;
    int g = lane >> 2, tig = lane & 3;
    int wm = (warp >> 2) * 64;
    int wn = (warp & 3) * 32;

    float acc[4][4][4];
    #pragma unroll
    for (int mt = 0; mt < 4; mt++)
        #pragma unroll
        for (int nt = 0; nt < 4; nt++)
            #pragma unroll
            for (int i = 0; i < 4; i++) acc[mt][nt][i] = 0.f;

    for (int k0 = 0; k0 < Cc; k0 += 32) {
        #pragma unroll
        for (int l = 0; l < 4; l++) {
            int e   = tid + l * 256;
            int row = e >> 3;
            int kq  = (e & 7) * 4;
            float4 v = *(const float4*)(g_M + (size_t)(i0 + row) * Cc + k0 + kq);
            *(uint4*)&As[row * GP + kq] =
                make_uint4(f2tf(v.x), f2tf(v.y), f2tf(v.z), f2tf(v.w));
        }
        #pragma unroll
        for (int l = 0; l < 4; l++) {
            int e  = tid + l * 256;
            int kr = e >> 5;
            int nq = (e & 31) * 4;
            int hw = j0 + nq;
            float4 v = make_float4(0.f, 0.f, 0.f, 0.f);
            if (hw < HWs)
                v = *(const float4*)(Xb + (size_t)(k0 + kr) * HWs + hw);
            *(uint4*)&Bs[kr * BP + nq] =
                make_uint4(f2tf(v.x), f2tf(v.y), f2tf(v.z), f2tf(v.w));
        }
        __syncthreads();

        #pragma unroll
        for (int ks = 0; ks < 32; ks += 8) {
            uint32_t af[4][4], bf[4][2];
            #pragma unroll
            for (int mt = 0; mt < 4; mt++) {
                int r = wm + mt * 16 + g;
                af[mt][0] = As[r       * GP + ks + tig];
                af[mt][1] = As[(r + 8) * GP + ks + tig];
                af[mt][2] = As[r       * GP + ks + tig + 4];
                af[mt][3] = As[(r + 8) * GP + ks + tig + 4];
            }
            #pragma unroll
            for (int nt = 0; nt < 4; nt++) {
                int c = wn + nt * 8 + g;
                bf[nt][0] = Bs[(ks + tig)     * BP + c];
                bf[nt][1] = Bs[(ks + tig + 4) * BP + c];
            }
            #pragma unroll
            for (int mt = 0; mt < 4; mt++)
                #pragma unroll
                for (int nt = 0; nt < 4; nt++)
                    mma8(acc[mt][nt], af[mt], bf[nt]);
        }
        __syncthreads();
    }

    #pragma unroll
    for (int mt = 0; mt < 4; mt++) {
        int m_  = wm + mt * 16 + g;
        int gi0 = i0 + m_;
        int gi1 = gi0 + 8;
        float bv0 = g_bias[gi0];
        float bv1 = g_bias[gi1];
        float* orow0 = Out + ((size_t)b * Cc + gi0) * HWs;
        float* orow1 = Out + ((size_t)b * Cc + gi1) * HWs;
        #pragma unroll
        for (int nt = 0; nt < 4; nt++) {
            int col = j0 + wn + nt * 8 + 2 * tig;
            if (col < HWs) {
                float2 v0 = make_float2(acc[mt][nt][0] - bv0, acc[mt][nt][1] - bv0);
                float2 v1 = make_float2(acc[mt][nt][2] - bv1, acc[mt][nt][3] - bv1);
                *(float2*)(orow0 + col) = v0;
                *(float2*)(orow1 + col) = v1;
            }
        }
    }
}

// ---------------------------------------------------------------- launch
extern "C" void kernel_launch(void* const* d_in, const int* in_sizes, int n_in,
                              void* d_out, int out_size)
{
    const float* X   = (const float*)d_in[0];
    const float* rot = (const float*)d_in[1];
    float* Out = (float*)d_out;

    k_zero<<<(Cc*Cc + 255) / 256, 256>>>();
    k_gram<<<dim3(10, Bb), 256>>>(X);          // also produces g_sum
    k_ns<<<NS_NB, 256>>>(rot);                 // prep + NS + rot@P + bias
    k_out<<<dim3(25, 4, Bb), 256>>>(X, Out);
}